// round 12
// baseline (speedup 1.0000x reference)
#include <cuda_runtime.h>

// Problem constants
#define BATCH 8
#define SEQ   1024
#define DIM   1024
#define NHEAD 16
#define HDIM  64

// Scratch layout (element offsets into g_scratch)
#define QOFF 0
#define KOFF (8u * 1024u * 1024u)
#define VOFF (16u * 1024u * 1024u)
#define POFF (24u * 1024u * 1024u)

// 128 MB static device scratch (allocation-free per harness rules)
__device__ float g_scratch[32u * 1024u * 1024u];

// SGEMM tiling
#define BM 128
#define BN 128
#define BK 8

// ---------------------------------------------------------------------------
// Kernel 1: projection GEMM with bias + scale.
//   C[m,n] = alpha * (sum_k A[m,k] * W[k,n] + bias[n])
//   A: (8192 x 1024) row-major (input), W: (1024 x 1024) row-major,
//   C -> g_scratch + c_off.
// ---------------------------------------------------------------------------
__global__ __launch_bounds__(256, 2)
void proj_gemm(const float* __restrict__ A, const float* __restrict__ W,
               const float* __restrict__ bias, unsigned c_off, float alpha) {
    __shared__ float As[BK][BM];
    __shared__ float Bs[BK][BN];
    const int K = DIM, N = DIM;

    int tid = threadIdx.x;
    int tx = tid & 15;        // 0..15 -> 8 output cols each
    int ty = tid >> 4;        // 0..15 -> 8 output rows each
    int bm = blockIdx.y * BM;
    int bn = blockIdx.x * BN;

    // A tile loader: 128 rows x 8 k-cols; thread loads one float4
    int arow = tid >> 1;           // 0..127
    int acol = (tid & 1) * 4;      // 0 or 4
    // W tile loader: 8 k-rows x 128 n-cols
    int wrow = tid >> 5;           // 0..7
    int wcol = (tid & 31) * 4;     // 0..124

    const float* Ap = A + (size_t)(bm + arow) * K + acol;
    const float* Wp = W + (size_t)wrow * N + bn + wcol;

    float acc[8][8];
#pragma unroll
    for (int i = 0; i < 8; i++)
#pragma unroll
        for (int j = 0; j < 8; j++) acc[i][j] = 0.0f;

    for (int k0 = 0; k0 < K; k0 += BK) {
        float4 av = *(const float4*)Ap; Ap += BK;
        float4 wv = *(const float4*)Wp; Wp += (size_t)BK * N;
        __syncthreads();
        As[acol + 0][arow] = av.x;
        As[acol + 1][arow] = av.y;
        As[acol + 2][arow] = av.z;
        As[acol + 3][arow] = av.w;
        *(float4*)&Bs[wrow][wcol] = wv;
        __syncthreads();
#pragma unroll
        for (int kk = 0; kk < BK; ++kk) {
            float a[8], b[8];
#pragma unroll
            for (int i = 0; i < 8; i++) a[i] = As[kk][ty * 8 + i];
#pragma unroll
            for (int j = 0; j < 8; j++) b[j] = Bs[kk][tx * 8 + j];
#pragma unroll
            for (int i = 0; i < 8; i++)
#pragma unroll
                for (int j = 0; j < 8; j++)
                    acc[i][j] += a[i] * b[j];
        }
    }

    float* C = g_scratch + c_off;
    int n0 = bn + tx * 8;
    float bb[8];
#pragma unroll
    for (int j = 0; j < 8; j++) bb[j] = bias[n0 + j];
#pragma unroll
    for (int i = 0; i < 8; i++) {
        int m = bm + ty * 8 + i;
        float4 v0, v1;
        v0.x = alpha * (acc[i][0] + bb[0]);
        v0.y = alpha * (acc[i][1] + bb[1]);
        v0.z = alpha * (acc[i][2] + bb[2]);
        v0.w = alpha * (acc[i][3] + bb[3]);
        v1.x = alpha * (acc[i][4] + bb[4]);
        v1.y = alpha * (acc[i][5] + bb[5]);
        v1.z = alpha * (acc[i][6] + bb[6]);
        v1.w = alpha * (acc[i][7] + bb[7]);
        *(float4*)(C + (size_t)m * N + n0)     = v0;
        *(float4*)(C + (size_t)m * N + n0 + 4) = v1;
    }
}

// ---------------------------------------------------------------------------
// Kernel 2: batched scores GEMM (NT):
//   P[b][i][j] = sum_d Q[b][i][d] * K[b][j][d]   (1/8 already folded into Q)
// ---------------------------------------------------------------------------
__global__ __launch_bounds__(256, 2)
void scores_gemm() {
    __shared__ float As[BK][BM];
    __shared__ float Bs[BK][BN];
    const int K = DIM;

    int bz = blockIdx.z;
    const float* A  = g_scratch + QOFF + (size_t)bz * SEQ * DIM;
    const float* Bm = g_scratch + KOFF + (size_t)bz * SEQ * DIM;
    float*       C  = g_scratch + POFF + (size_t)bz * SEQ * SEQ;

    int tid = threadIdx.x;
    int tx = tid & 15, ty = tid >> 4;
    int bm = blockIdx.y * BM, bn = blockIdx.x * BN;

    int arow = tid >> 1;
    int acol = (tid & 1) * 4;

    const float* Ap = A  + (size_t)(bm + arow) * K + acol;
    const float* Bp = Bm + (size_t)(bn + arow) * K + acol;  // NT: B rows are n-index

    float acc[8][8];
#pragma unroll
    for (int i = 0; i < 8; i++)
#pragma unroll
        for (int j = 0; j < 8; j++) acc[i][j] = 0.0f;

    for (int k0 = 0; k0 < K; k0 += BK) {
        float4 av = *(const float4*)Ap; Ap += BK;
        float4 bv = *(const float4*)Bp; Bp += BK;
        __syncthreads();
        As[acol + 0][arow] = av.x;
        As[acol + 1][arow] = av.y;
        As[acol + 2][arow] = av.z;
        As[acol + 3][arow] = av.w;
        Bs[acol + 0][arow] = bv.x;
        Bs[acol + 1][arow] = bv.y;
        Bs[acol + 2][arow] = bv.z;
        Bs[acol + 3][arow] = bv.w;
        __syncthreads();
#pragma unroll
        for (int kk = 0; kk < BK; ++kk) {
            float a[8], b[8];
#pragma unroll
            for (int i = 0; i < 8; i++) a[i] = As[kk][ty * 8 + i];
#pragma unroll
            for (int j = 0; j < 8; j++) b[j] = Bs[kk][tx * 8 + j];
#pragma unroll
            for (int i = 0; i < 8; i++)
#pragma unroll
                for (int j = 0; j < 8; j++)
                    acc[i][j] += a[i] * b[j];
        }
    }

    int n0 = bn + tx * 8;
#pragma unroll
    for (int i = 0; i < 8; i++) {
        int m = bm + ty * 8 + i;
        float4 v0 = make_float4(acc[i][0], acc[i][1], acc[i][2], acc[i][3]);
        float4 v1 = make_float4(acc[i][4], acc[i][5], acc[i][6], acc[i][7]);
        *(float4*)(C + (size_t)m * SEQ + n0)     = v0;
        *(float4*)(C + (size_t)m * SEQ + n0 + 4) = v1;
    }
}

// ---------------------------------------------------------------------------
// Kernel 3: masked softmax over rows of P (in place).
//   s += (1 - mask) * -1e9; p = softmax(s)
// One block (256 threads) per row of 1024; each thread owns one float4.
// ---------------------------------------------------------------------------
__global__ __launch_bounds__(256)
void softmax_kernel(const float* __restrict__ mask) {
    __shared__ float red[8];
    float* P = g_scratch + POFF;
    int row = blockIdx.x;                 // b*SEQ + q
    int b   = row >> 10;
    int q   = row & (SEQ - 1);
    float* p = P + (size_t)row * SEQ;
    const float* mrow = mask + ((size_t)b * SEQ + q) * SEQ;

    int t = threadIdx.x;
    float4 s  = ((const float4*)p)[t];
    float4 mm = ((const float4*)mrow)[t];
    s.x += (1.0f - mm.x) * -1e9f;
    s.y += (1.0f - mm.y) * -1e9f;
    s.z += (1.0f - mm.z) * -1e9f;
    s.w += (1.0f - mm.w) * -1e9f;

    // block max
    float v = fmaxf(fmaxf(s.x, s.y), fmaxf(s.z, s.w));
#pragma unroll
    for (int o = 16; o; o >>= 1) v = fmaxf(v, __shfl_xor_sync(0xffffffffu, v, o));
    if ((t & 31) == 0) red[t >> 5] = v;
    __syncthreads();
    if (t < 32) {
        float x = (t < 8) ? red[t] : -3.4e38f;
#pragma unroll
        for (int o = 4; o; o >>= 1) x = fmaxf(x, __shfl_xor_sync(0xffffffffu, x, o));
        if (t == 0) red[0] = x;
    }
    __syncthreads();
    float rmax = red[0];

    float e0 = expf(s.x - rmax);
    float e1 = expf(s.y - rmax);
    float e2 = expf(s.z - rmax);
    float e3 = expf(s.w - rmax);

    __syncthreads();  // done reading red[0] before reuse
    float sum = e0 + e1 + e2 + e3;
#pragma unroll
    for (int o = 16; o; o >>= 1) sum += __shfl_xor_sync(0xffffffffu, sum, o);
    if ((t & 31) == 0) red[t >> 5] = sum;
    __syncthreads();
    if (t < 32) {
        float x = (t < 8) ? red[t] : 0.0f;
#pragma unroll
        for (int o = 4; o; o >>= 1) x += __shfl_xor_sync(0xffffffffu, x, o);
        if (t == 0) red[0] = x;
    }
    __syncthreads();
    float inv = 1.0f / red[0];

    ((float4*)p)[t] = make_float4(e0 * inv, e1 * inv, e2 * inv, e3 * inv);
}

// ---------------------------------------------------------------------------
// Kernel 4: batched ctx GEMM (NN) with permuted output:
//   ctx[b][q][n] = sum_j P[b][q][j] * V[b][j][n]
//   out[b*S*D + (n/64)*S*64 + q*64 + (n%64)] = ctx[b][q][n]
// ---------------------------------------------------------------------------
__global__ __launch_bounds__(256, 2)
void ctx_gemm(float* __restrict__ out) {
    __shared__ float As[BK][BM];
    __shared__ float Bs[BK][BN];
    const int K = SEQ, N = DIM;

    int bz = blockIdx.z;
    const float* A = g_scratch + POFF + (size_t)bz * SEQ * SEQ;
    const float* V = g_scratch + VOFF + (size_t)bz * SEQ * DIM;

    int tid = threadIdx.x;
    int tx = tid & 15, ty = tid >> 4;
    int bm = blockIdx.y * BM, bn = blockIdx.x * BN;

    int arow = tid >> 1;
    int acol = (tid & 1) * 4;
    int vrow = tid >> 5;
    int vcol = (tid & 31) * 4;

    const float* Ap = A + (size_t)(bm + arow) * K + acol;
    const float* Vp = V + (size_t)vrow * N + bn + vcol;

    float acc[8][8];
#pragma unroll
    for (int i = 0; i < 8; i++)
#pragma unroll
        for (int j = 0; j < 8; j++) acc[i][j] = 0.0f;

    for (int k0 = 0; k0 < K; k0 += BK) {
        float4 av = *(const float4*)Ap; Ap += BK;
        float4 vv = *(const float4*)Vp; Vp += (size_t)BK * N;
        __syncthreads();
        As[acol + 0][arow] = av.x;
        As[acol + 1][arow] = av.y;
        As[acol + 2][arow] = av.z;
        As[acol + 3][arow] = av.w;
        *(float4*)&Bs[vrow][vcol] = vv;
        __syncthreads();
#pragma unroll
        for (int kk = 0; kk < BK; ++kk) {
            float a[8], b[8];
#pragma unroll
            for (int i = 0; i < 8; i++) a[i] = As[kk][ty * 8 + i];
#pragma unroll
            for (int j = 0; j < 8; j++) b[j] = Bs[kk][tx * 8 + j];
#pragma unroll
            for (int i = 0; i < 8; i++)
#pragma unroll
                for (int j = 0; j < 8; j++)
                    acc[i][j] += a[i] * b[j];
        }
    }

    // Permuted epilogue. Each thread's 8 cols are [n0, n0+7], n0 % 8 == 0,
    // so they live in a single head h = n0/64, dh = n0%64 .. +7.
    int n0 = bn + tx * 8;
    int h  = n0 >> 6;
    int dh = n0 & 63;
    float* obase = out + (size_t)bz * SEQ * DIM + (size_t)h * SEQ * HDIM + dh;
#pragma unroll
    for (int i = 0; i < 8; i++) {
        int m = bm + ty * 8 + i;
        float4 v0 = make_float4(acc[i][0], acc[i][1], acc[i][2], acc[i][3]);
        float4 v1 = make_float4(acc[i][4], acc[i][5], acc[i][6], acc[i][7]);
        *(float4*)(obase + (size_t)m * HDIM)     = v0;
        *(float4*)(obase + (size_t)m * HDIM + 4) = v1;
    }
}

// ---------------------------------------------------------------------------
// Launch
// ---------------------------------------------------------------------------
extern "C" void kernel_launch(void* const* d_in, const int* in_sizes, int n_in,
                              void* d_out, int out_size) {
    const float* hidden = (const float*)d_in[0];
    const float* right  = (const float*)d_in[1];
    const float* mask   = (const float*)d_in[2];
    const float* Wq     = (const float*)d_in[3];
    const float* bq     = (const float*)d_in[4];
    const float* Wk     = (const float*)d_in[5];
    const float* bk     = (const float*)d_in[6];
    const float* Wv     = (const float*)d_in[7];
    const float* bv     = (const float*)d_in[8];
    float* out = (float*)d_out;

    dim3 gproj(DIM / BN, (BATCH * SEQ) / BM);      // (8, 64)
    dim3 gbat(SEQ / BN, SEQ / BM, BATCH);          // (8, 8, 8)

    // Fold 1/sqrt(64) = 0.125 (exact power of two) into Q.
    proj_gemm<<<gproj, 256>>>(hidden, Wq, bq, QOFF, 0.125f);
    proj_gemm<<<gproj, 256>>>(right,  Wk, bk, KOFF, 1.0f);
    proj_gemm<<<gproj, 256>>>(right,  Wv, bv, VOFF, 1.0f);
    scores_gemm<<<gbat, 256>>>();
    softmax_kernel<<<BATCH * SEQ, 256>>>(mask);
    ctx_gemm<<<gbat, 256>>>(out);
}

// round 14
// speedup vs baseline: 2.8986x; 2.8986x over previous
#include <cuda_runtime.h>
#include <cstdint>

// ============================================================================
// Problem constants
// ============================================================================
#define BATCH 8
#define SEQ   1024
#define DIM   1024
#define HDIM  64
#define KTOT  1024

// ============================================================================
// Scratch layout (element offsets into g_scratch)
// ============================================================================
#define NF (1u << 20)
#define Q_OFF   (0u  * NF)
#define K_OFF   (8u  * NF)
#define V_OFF   (16u * NF)
#define VT_OFF  (24u * NF)
#define P_OFF   (32u * NF)
#define WQT_OFF (40u * NF)
#define WKT_OFF (41u * NF)
#define WVT_OFF (42u * NF)

__device__ __align__(256) float g_scratch[43u * NF];

// ============================================================================
// GEMM tiling
// ============================================================================
#define BM     128
#define BN     128
#define BKF    32               // k floats per stage
#define SA     36               // padded smem row stride (floats)
#define STAGES 3
#define NKI    (KTOT / BKF)     // 32
#define STAGE_FLOATS (BM * SA)  // 4608 floats per matrix per stage
#define SMEM_BYTES (2 * STAGES * STAGE_FLOATS * 4)   // 110592

// ============================================================================
// Device helpers
// ============================================================================
__device__ __forceinline__ uint32_t smem_u32(const void* p) {
    uint32_t a;
    asm("{ .reg .u64 t; cvta.to.shared.u64 t, %1; cvt.u32.u64 %0, t; }"
        : "=r"(a) : "l"(p));
    return a;
}

__device__ __forceinline__ void cp_async16(uint32_t saddr, const void* gaddr) {
    asm volatile("cp.async.cg.shared.global [%0], [%1], 16;"
                 :: "r"(saddr), "l"(gaddr) : "memory");
}

// fp32 -> tf32 round-to-nearest (result bits usable directly by mma.tf32)
__device__ __forceinline__ uint32_t f2tf(float x) {
    uint32_t r;
    asm("cvt.rna.tf32.f32 %0, %1;" : "=r"(r) : "f"(x));
    return r;
}

__device__ __forceinline__ void mma8(float* c, const uint32_t* a, const uint32_t* b) {
    asm volatile(
        "mma.sync.aligned.m16n8k8.row.col.f32.tf32.tf32.f32 "
        "{%0,%1,%2,%3}, {%4,%5,%6,%7}, {%8,%9}, {%0,%1,%2,%3};"
        : "+f"(c[0]), "+f"(c[1]), "+f"(c[2]), "+f"(c[3])
        : "r"(a[0]), "r"(a[1]), "r"(a[2]), "r"(a[3]), "r"(b[0]), "r"(b[1]));
}

// ============================================================================
// tf32 tensor-core GEMM:  D[BM x BN] = A[BM x K] . B[BN x K]^T
// (A row-major, B K-major; both fp32 in gmem, cvt.rna to tf32 in-kernel)
// mode 0: C[gm][gn] = alpha*(acc + bias[gn]);  rows = by*BM          (proj)
// mode 1: C[gm][gn] = acc;  rows = bz*SEQ + by*BM                    (scores)
// mode 2: permuted: out[bz][gn/64][q][gn%64] = acc                   (context)
// ============================================================================
__global__ __launch_bounds__(256, 1)
void mma_gemm(const float* __restrict__ A, const float* __restrict__ B,
              float* __restrict__ C, const float* __restrict__ bias,
              float alpha, int mode) {
    extern __shared__ float sm[];
    float* As = sm;                          // [STAGES][BM][SA]
    float* Bs = sm + STAGES * STAGE_FLOATS;  // [STAGES][BN][SA]
    uint32_t sAb = smem_u32(As);
    uint32_t sBb = smem_u32(Bs);

    int tid = threadIdx.x;
    int wid = tid >> 5, lane = tid & 31;
    int wm = wid >> 2, wn = wid & 3;         // warp grid 2 x 4
    int bx = blockIdx.x, by = blockIdx.y, bz = blockIdx.z;

    int aRow = (mode == 0 ? 0 : bz * SEQ) + by * BM;
    int bRow = (mode == 0 ? 0 : bz * SEQ) + bx * BN;
    const float* Ag = A + (size_t)aRow * KTOT;
    const float* Bg = B + (size_t)bRow * KTOT;

    // per-thread cp.async assignments: idx = i*256+tid; row = idx/8, c4 = idx%8
    int ldrow[4], ldc4[4];
#pragma unroll
    for (int i = 0; i < 4; i++) {
        int idx = i * 256 + tid;
        ldrow[i] = idx >> 3;
        ldc4[i] = idx & 7;
    }

    float acc[4][4][4];
#pragma unroll
    for (int mi = 0; mi < 4; mi++)
#pragma unroll
        for (int ni = 0; ni < 4; ni++)
#pragma unroll
            for (int c = 0; c < 4; c++) acc[mi][ni][c] = 0.0f;

    // ---- prologue: fill STAGES stages ----
#pragma unroll
    for (int s = 0; s < STAGES; s++) {
#pragma unroll
        for (int i = 0; i < 4; i++) {
            uint32_t soff = ((s * BM + ldrow[i]) * SA + ldc4[i] * 4) * 4;
            const float* ga = Ag + (size_t)ldrow[i] * KTOT + s * BKF + ldc4[i] * 4;
            const float* gb = Bg + (size_t)ldrow[i] * KTOT + s * BKF + ldc4[i] * 4;
            cp_async16(sAb + soff, ga);
            cp_async16(sBb + soff, gb);
        }
        asm volatile("cp.async.commit_group;" ::: "memory");
    }

    int lr = lane >> 2;      // 0..7
    int lc = lane & 3;       // 0..3

    // ---- main loop ----
    for (int ks = 0; ks < NKI; ks++) {
        int st = ks % STAGES;
        asm volatile("cp.async.wait_group %0;" :: "n"(STAGES - 1) : "memory");
        __syncthreads();

        const float* Ast = As + st * STAGE_FLOATS;
        const float* Bst = Bs + st * STAGE_FLOATS;

#pragma unroll
        for (int k8 = 0; k8 < BKF / 8; k8++) {
            int kk = k8 * 8;
            uint32_t afr[4][4];
#pragma unroll
            for (int mi = 0; mi < 4; mi++) {
                const float* base = Ast + (wm * 64 + mi * 16 + lr) * SA + kk + lc;
                afr[mi][0] = f2tf(base[0]);
                afr[mi][1] = f2tf(base[8 * SA]);
                afr[mi][2] = f2tf(base[4]);
                afr[mi][3] = f2tf(base[8 * SA + 4]);
            }
            uint32_t bfr[4][2];
#pragma unroll
            for (int ni = 0; ni < 4; ni++) {
                const float* base = Bst + (wn * 32 + ni * 8 + lr) * SA + kk + lc;
                bfr[ni][0] = f2tf(base[0]);
                bfr[ni][1] = f2tf(base[4]);
            }
#pragma unroll
            for (int mi = 0; mi < 4; mi++)
#pragma unroll
                for (int ni = 0; ni < 4; ni++)
                    mma8(acc[mi][ni], afr[mi], bfr[ni]);
        }
        __syncthreads();

        int kn = ks + STAGES;
        if (kn < NKI) {
#pragma unroll
            for (int i = 0; i < 4; i++) {
                uint32_t soff = ((st * BM + ldrow[i]) * SA + ldc4[i] * 4) * 4;
                const float* ga = Ag + (size_t)ldrow[i] * KTOT + kn * BKF + ldc4[i] * 4;
                const float* gb = Bg + (size_t)ldrow[i] * KTOT + kn * BKF + ldc4[i] * 4;
                cp_async16(sAb + soff, ga);
                cp_async16(sBb + soff, gb);
            }
        }
        asm volatile("cp.async.commit_group;" ::: "memory");  // keep group count fixed
    }

    // ---- epilogue ----
    int crow = lr;                 // row within 16-row tile
    int ccol = (lane & 3) * 2;     // col within 8-col tile

    if (mode != 2) {
#pragma unroll
        for (int mi = 0; mi < 4; mi++) {
            int gm = aRow + wm * 64 + mi * 16 + crow;
            float* crow0 = C + (size_t)gm * DIM;
            float* crow1 = crow0 + (size_t)8 * DIM;
#pragma unroll
            for (int ni = 0; ni < 4; ni++) {
                int gn = bx * BN + wn * 32 + ni * 8 + ccol;
                const float* a4 = acc[mi][ni];
                if (mode == 0) {
                    float b0 = bias[gn], b1 = bias[gn + 1];
                    *(float2*)(crow0 + gn) =
                        make_float2(alpha * (a4[0] + b0), alpha * (a4[1] + b1));
                    *(float2*)(crow1 + gn) =
                        make_float2(alpha * (a4[2] + b0), alpha * (a4[3] + b1));
                } else {
                    *(float2*)(crow0 + gn) = make_float2(a4[0], a4[1]);
                    *(float2*)(crow1 + gn) = make_float2(a4[2], a4[3]);
                }
            }
        }
    } else {
#pragma unroll
        for (int mi = 0; mi < 4; mi++) {
            int q = by * BM + wm * 64 + mi * 16 + crow;   // row within batch
#pragma unroll
            for (int ni = 0; ni < 4; ni++) {
                int gn = bx * BN + wn * 32 + ni * 8 + ccol;
                int h = gn >> 6, dh = gn & 63;
                float* dst = C + (size_t)bz * SEQ * DIM +
                             ((size_t)h * SEQ + q) * HDIM + dh;
                const float* a4 = acc[mi][ni];
                *(float2*)dst = make_float2(a4[0], a4[1]);
                *(float2*)(dst + (size_t)8 * HDIM) = make_float2(a4[2], a4[3]);
            }
        }
    }
}

// ============================================================================
// 1024x1024 transpose: dst[c][r] = src[r][c] (optionally batched via z)
// ============================================================================
__global__ __launch_bounds__(256)
void transpose_k(const float* __restrict__ src, float* __restrict__ dst,
                 int src_bstride, int dst_bstride) {
    __shared__ float t[32][33];
    int bz = blockIdx.z;
    const float* s = src + (size_t)bz * src_bstride;
    float* d = dst + (size_t)bz * dst_bstride;
    int x = blockIdx.x * 32 + threadIdx.x;
    int y0 = blockIdx.y * 32;
    for (int i = threadIdx.y; i < 32; i += 8)
        t[i][threadIdx.x] = s[(size_t)(y0 + i) * 1024 + x];
    __syncthreads();
    int ox = blockIdx.y * 32 + threadIdx.x;
    int oy0 = blockIdx.x * 32;
    for (int i = threadIdx.y; i < 32; i += 8)
        d[(size_t)(oy0 + i) * 1024 + ox] = t[threadIdx.x][i];
}

// ============================================================================
// Masked softmax over rows of P (in place).
// ============================================================================
__global__ __launch_bounds__(256)
void softmax_kernel(const float* __restrict__ mask) {
    __shared__ float red[8];
    float* P = g_scratch + P_OFF;
    int row = blockIdx.x;
    int b = row >> 10;
    int q = row & (SEQ - 1);
    float* p = P + (size_t)row * SEQ;
    const float* mrow = mask + ((size_t)b * SEQ + q) * SEQ;

    int t = threadIdx.x;
    float4 s = ((const float4*)p)[t];
    float4 mm = ((const float4*)mrow)[t];
    s.x += (1.0f - mm.x) * -1e9f;
    s.y += (1.0f - mm.y) * -1e9f;
    s.z += (1.0f - mm.z) * -1e9f;
    s.w += (1.0f - mm.w) * -1e9f;

    float v = fmaxf(fmaxf(s.x, s.y), fmaxf(s.z, s.w));
#pragma unroll
    for (int o = 16; o; o >>= 1) v = fmaxf(v, __shfl_xor_sync(0xffffffffu, v, o));
    if ((t & 31) == 0) red[t >> 5] = v;
    __syncthreads();
    if (t < 32) {
        float x = (t < 8) ? red[t] : -3.4e38f;
#pragma unroll
        for (int o = 4; o; o >>= 1) x = fmaxf(x, __shfl_xor_sync(0xffffffffu, x, o));
        if (t == 0) red[0] = x;
    }
    __syncthreads();
    float rmax = red[0];

    float e0 = expf(s.x - rmax);
    float e1 = expf(s.y - rmax);
    float e2 = expf(s.z - rmax);
    float e3 = expf(s.w - rmax);

    __syncthreads();
    float sum = e0 + e1 + e2 + e3;
#pragma unroll
    for (int o = 16; o; o >>= 1) sum += __shfl_xor_sync(0xffffffffu, sum, o);
    if ((t & 31) == 0) red[t >> 5] = sum;
    __syncthreads();
    if (t < 32) {
        float x = (t < 8) ? red[t] : 0.0f;
#pragma unroll
        for (int o = 4; o; o >>= 1) x += __shfl_xor_sync(0xffffffffu, x, o);
        if (t == 0) red[0] = x;
    }
    __syncthreads();
    float inv = 1.0f / red[0];

    ((float4*)p)[t] = make_float4(e0 * inv, e1 * inv, e2 * inv, e3 * inv);
}

// ============================================================================
// Launch
// ============================================================================
extern "C" void kernel_launch(void* const* d_in, const int* in_sizes, int n_in,
                              void* d_out, int out_size) {
    const float* hidden = (const float*)d_in[0];
    const float* right  = (const float*)d_in[1];
    const float* mask   = (const float*)d_in[2];
    const float* Wq     = (const float*)d_in[3];
    const float* bq     = (const float*)d_in[4];
    const float* Wk     = (const float*)d_in[5];
    const float* bk     = (const float*)d_in[6];
    const float* Wv     = (const float*)d_in[7];
    const float* bv     = (const float*)d_in[8];
    float* out = (float*)d_out;

    float* S = nullptr;
    cudaGetSymbolAddress((void**)&S, g_scratch);
    cudaFuncSetAttribute(mma_gemm, cudaFuncAttributeMaxDynamicSharedMemorySize,
                         SMEM_BYTES);

    // 1) transpose weights to K-major [n][k]
    transpose_k<<<dim3(32, 32, 1), dim3(32, 8)>>>(Wq, S + WQT_OFF, 0, 0);
    transpose_k<<<dim3(32, 32, 1), dim3(32, 8)>>>(Wk, S + WKT_OFF, 0, 0);
    transpose_k<<<dim3(32, 32, 1), dim3(32, 8)>>>(Wv, S + WVT_OFF, 0, 0);

    // 2) projections (mode 0); 1/sqrt(64) = 0.125 exact, folded into Q
    dim3 gproj(DIM / BN, (BATCH * SEQ) / BM, 1);   // (8, 64, 1)
    mma_gemm<<<gproj, 256, SMEM_BYTES>>>(hidden, S + WQT_OFF, S + Q_OFF, bq, 0.125f, 0);
    mma_gemm<<<gproj, 256, SMEM_BYTES>>>(right,  S + WKT_OFF, S + K_OFF, bk, 1.0f,   0);
    mma_gemm<<<gproj, 256, SMEM_BYTES>>>(right,  S + WVT_OFF, S + V_OFF, bv, 1.0f,   0);

    // 3) transpose V per batch -> VT[b][d][s]
    transpose_k<<<dim3(32, 32, BATCH), dim3(32, 8)>>>(
        S + V_OFF, S + VT_OFF, SEQ * DIM, SEQ * DIM);

    // 4) scores (mode 1): P[b][i][j] = Q[b,i,:] . K[b,j,:]
    dim3 gbat(SEQ / BN, SEQ / BM, BATCH);          // (8, 8, 8)
    mma_gemm<<<gbat, 256, SMEM_BYTES>>>(S + Q_OFF, S + K_OFF, S + P_OFF, bq, 1.0f, 1);

    // 5) masked softmax
    softmax_kernel<<<BATCH * SEQ, 256>>>(mask);

    // 6) context (mode 2): out[b][h][q][dh] = sum_j P[b][q][j] * VT[b][h*64+dh][j]
    mma_gemm<<<gbat, 256, SMEM_BYTES>>>(S + P_OFF, S + VT_OFF, out, bq, 1.0f, 2);
}

// round 15
// speedup vs baseline: 5.7890x; 1.9971x over previous
#include <cuda_runtime.h>
#include <cuda_fp16.h>
#include <cstdint>

// ============================================================================
// Problem constants
// ============================================================================
#define BATCH 8
#define SEQ   1024
#define DIM   1024
#define HDIM  64

// ============================================================================
// Scratch (half + fp32 scores), element offsets
// ============================================================================
#define H1M (1u << 20)
#define XH  (0u  * H1M)   // hidden as fp16          (8M)
#define RH  (8u  * H1M)   // right as fp16           (8M)
#define QH  (16u * H1M)   // Q fp16 (scaled 0.125)   (8M)
#define KH  (24u * H1M)   // K fp16                  (8M)
#define VH  (32u * H1M)   // V fp16 [s][d]           (8M)
#define VTH (40u * H1M)   // V^T fp16 [d][s]         (8M)
#define PH  (48u * H1M)   // probs fp16              (8M)
#define WQ  (56u * H1M)   // Wq^T fp16 [n][k]; WK=+1M, WV=+2M

__device__ __align__(256) __half g_half[59u * H1M];
__device__ __align__(256) float  g_scores[8u * H1M];   // fp32 scores (32MB)

// ============================================================================
// GEMM tiling
// ============================================================================
#define BM     128
#define BN     128
#define BKH    64                 // halfs of K per stage (128 B/row)
#define SA     72                 // padded smem row stride (halfs, 144 B)
#define STAGES 4
#define NKI    (1024 / BKH)       // 16
#define SMEM_BYTES (STAGES * (BM + BN) * SA * 2)   // 147456

// ============================================================================
// Device helpers
// ============================================================================
__device__ __forceinline__ uint32_t smem_u32(const void* p) {
    uint32_t a;
    asm("{ .reg .u64 t; cvta.to.shared.u64 t, %1; cvt.u32.u64 %0, t; }"
        : "=r"(a) : "l"(p));
    return a;
}

__device__ __forceinline__ void cp_async16(uint32_t saddr, const void* gaddr) {
    asm volatile("cp.async.cg.shared.global [%0], [%1], 16;"
                 :: "r"(saddr), "l"(gaddr) : "memory");
}

#define LDSM4(r0, r1, r2, r3, addr) \
    asm volatile("ldmatrix.sync.aligned.m8n8.x4.shared.b16 {%0,%1,%2,%3}, [%4];" \
                 : "=r"(r0), "=r"(r1), "=r"(r2), "=r"(r3) : "r"(addr))

__device__ __forceinline__ void mma16816(float* c, const uint32_t* a,
                                         const uint32_t* b) {
    asm volatile(
        "mma.sync.aligned.m16n8k16.row.col.f32.f16.f16.f32 "
        "{%0,%1,%2,%3}, {%4,%5,%6,%7}, {%8,%9}, {%0,%1,%2,%3};"
        : "+f"(c[0]), "+f"(c[1]), "+f"(c[2]), "+f"(c[3])
        : "r"(a[0]), "r"(a[1]), "r"(a[2]), "r"(a[3]), "r"(b[0]), "r"(b[1]));
}

// ============================================================================
// fp16 tensor-core GEMM:  D[BM x BN] = A[BM x 1024] . B[BN x 1024]^T
// (A row-major halfs, B K-major halfs; fp32 accumulate)
// MODE 0: merged projections (z: 0=Q,1=K,2=V), half output with bias+alpha
// MODE 1: scores -> g_scores fp32
// MODE 2: context -> permuted fp32 out
// ============================================================================
template <int MODE>
__global__ __launch_bounds__(256, 1)
void hgemm(const float* __restrict__ b0, const float* __restrict__ b1,
           const float* __restrict__ b2, float* __restrict__ outp) {
    extern __shared__ __half smh[];
    __half* As = smh;                            // [STAGES][BM][SA]
    __half* Bs = smh + STAGES * BM * SA;         // [STAGES][BN][SA]
    uint32_t sAb = smem_u32(As);
    uint32_t sBb = smem_u32(Bs);

    int tid = threadIdx.x;
    int wid = tid >> 5, lane = tid & 31;
    int wm = wid >> 2, wn = wid & 3;             // 2 x 4 warp grid
    int bx = blockIdx.x, by = blockIdx.y, bz = blockIdx.z;

    // ---- resolve operands from scratch ----
    const __half *Ag, *Bg;
    if (MODE == 0) {
        Ag = g_half + (bz == 0 ? XH : RH) + (size_t)by * BM * 1024;
        Bg = g_half + WQ + (size_t)bz * H1M + (size_t)bx * BN * 1024;
    } else if (MODE == 1) {
        Ag = g_half + QH + (size_t)bz * H1M + (size_t)by * BM * 1024;
        Bg = g_half + KH + (size_t)bz * H1M + (size_t)bx * BN * 1024;
    } else {
        Ag = g_half + PH + (size_t)bz * H1M + (size_t)by * BM * 1024;
        Bg = g_half + VTH + (size_t)bz * H1M + (size_t)bx * BN * 1024;
    }

    // ---- loader assignments: 1024 16B-chunks per matrix per stage ----
    int ldrow[4], ldc[4];
#pragma unroll
    for (int i = 0; i < 4; i++) {
        int idx = i * 256 + tid;
        ldrow[i] = idx >> 3;
        ldc[i] = idx & 7;
    }

    // ---- fragment smem byte offsets (within one stage) ----
    int r8 = lane & 7;
    int a_row = ((lane >> 3) & 1) * 8 + r8;
    int a_k   = (lane >> 4) * 8;
    uint32_t aoff[4];
#pragma unroll
    for (int mi = 0; mi < 4; mi++)
        aoff[mi] = ((wm * 64 + mi * 16 + a_row) * SA + a_k) * 2;
    int b_n = ((lane >> 4) & 1) * 8 + r8;
    int b_k = ((lane >> 3) & 1) * 8;
    uint32_t boff[2];
#pragma unroll
    for (int g = 0; g < 2; g++)
        boff[g] = ((wn * 32 + g * 16 + b_n) * SA + b_k) * 2;

    float acc[4][4][4];
#pragma unroll
    for (int mi = 0; mi < 4; mi++)
#pragma unroll
        for (int ni = 0; ni < 4; ni++)
#pragma unroll
            for (int c = 0; c < 4; c++) acc[mi][ni][c] = 0.0f;

    // ---- prologue: fill STAGES stages ----
#pragma unroll
    for (int s = 0; s < STAGES; s++) {
#pragma unroll
        for (int i = 0; i < 4; i++) {
            uint32_t so = (uint32_t)(ldrow[i] * SA + ldc[i] * 8) * 2;
            uint32_t sb = (uint32_t)(s * BM * SA * 2);
            cp_async16(sAb + sb + so, Ag + (size_t)ldrow[i] * 1024 + s * BKH + ldc[i] * 8);
            cp_async16(sBb + sb + so, Bg + (size_t)ldrow[i] * 1024 + s * BKH + ldc[i] * 8);
        }
        asm volatile("cp.async.commit_group;" ::: "memory");
    }

    // ---- main loop ----
    for (int ks = 0; ks < NKI; ks++) {
        int st = ks % STAGES;
        asm volatile("cp.async.wait_group %0;" :: "n"(STAGES - 1) : "memory");
        __syncthreads();

        uint32_t Ast = sAb + (uint32_t)(st * BM * SA * 2);
        uint32_t Bst = sBb + (uint32_t)(st * BN * SA * 2);

#pragma unroll
        for (int k16 = 0; k16 < BKH / 16; k16++) {
            uint32_t kk = k16 * 32;   // 16 halfs = 32 bytes
            uint32_t afr[4][4];
#pragma unroll
            for (int mi = 0; mi < 4; mi++)
                LDSM4(afr[mi][0], afr[mi][1], afr[mi][2], afr[mi][3],
                      Ast + aoff[mi] + kk);
            uint32_t bfr[4][2];
            LDSM4(bfr[0][0], bfr[0][1], bfr[1][0], bfr[1][1], Bst + boff[0] + kk);
            LDSM4(bfr[2][0], bfr[2][1], bfr[3][0], bfr[3][1], Bst + boff[1] + kk);
#pragma unroll
            for (int mi = 0; mi < 4; mi++)
#pragma unroll
                for (int ni = 0; ni < 4; ni++)
                    mma16816(acc[mi][ni], afr[mi], bfr[ni]);
        }
        __syncthreads();

        int kn = ks + STAGES;
        if (kn < NKI) {
#pragma unroll
            for (int i = 0; i < 4; i++) {
                uint32_t so = (uint32_t)(ldrow[i] * SA + ldc[i] * 8) * 2;
                uint32_t sb = (uint32_t)(st * BM * SA * 2);
                cp_async16(sAb + sb + so,
                           Ag + (size_t)ldrow[i] * 1024 + kn * BKH + ldc[i] * 8);
                cp_async16(sBb + sb + so,
                           Bg + (size_t)ldrow[i] * 1024 + kn * BKH + ldc[i] * 8);
            }
        }
        asm volatile("cp.async.commit_group;" ::: "memory");
    }

    // ---- epilogue ----
    int crow = lane >> 2;
    int ccol = (lane & 3) * 2;

    if (MODE == 0) {
        const float* bias = (bz == 0) ? b0 : (bz == 1 ? b1 : b2);
        float alpha = (bz == 0) ? 0.125f : 1.0f;
        __half* Ch = g_half + QH + (size_t)bz * 8 * H1M;
#pragma unroll
        for (int mi = 0; mi < 4; mi++) {
            int gm = by * BM + wm * 64 + mi * 16 + crow;
            __half* r0 = Ch + (size_t)gm * 1024;
            __half* r1 = r0 + (size_t)8 * 1024;
#pragma unroll
            for (int ni = 0; ni < 4; ni++) {
                int gn = bx * BN + wn * 32 + ni * 8 + ccol;
                const float* a4 = acc[mi][ni];
                float bb0 = bias[gn], bb1 = bias[gn + 1];
                *(half2*)(r0 + gn) =
                    __floats2half2_rn(alpha * (a4[0] + bb0), alpha * (a4[1] + bb1));
                *(half2*)(r1 + gn) =
                    __floats2half2_rn(alpha * (a4[2] + bb0), alpha * (a4[3] + bb1));
            }
        }
    } else if (MODE == 1) {
        float* Cf = g_scores + (size_t)bz * H1M;
#pragma unroll
        for (int mi = 0; mi < 4; mi++) {
            int gm = by * BM + wm * 64 + mi * 16 + crow;
            float* r0 = Cf + (size_t)gm * 1024;
            float* r1 = r0 + (size_t)8 * 1024;
#pragma unroll
            for (int ni = 0; ni < 4; ni++) {
                int gn = bx * BN + wn * 32 + ni * 8 + ccol;
                const float* a4 = acc[mi][ni];
                *(float2*)(r0 + gn) = make_float2(a4[0], a4[1]);
                *(float2*)(r1 + gn) = make_float2(a4[2], a4[3]);
            }
        }
    } else {
        float* obase = outp + (size_t)bz * SEQ * DIM;
#pragma unroll
        for (int mi = 0; mi < 4; mi++) {
            int q = by * BM + wm * 64 + mi * 16 + crow;
#pragma unroll
            for (int ni = 0; ni < 4; ni++) {
                int gn = bx * BN + wn * 32 + ni * 8 + ccol;
                int h = gn >> 6, dh = gn & 63;
                float* dst = obase + ((size_t)h * SEQ + q) * HDIM + dh;
                const float* a4 = acc[mi][ni];
                *(float2*)dst = make_float2(a4[0], a4[1]);
                *(float2*)(dst + (size_t)8 * HDIM) = make_float2(a4[2], a4[3]);
            }
        }
    }
}

// ============================================================================
// fp32 -> fp16 copy (8 elems / thread)
// ============================================================================
__global__ __launch_bounds__(256)
void f2h(const float4* __restrict__ src, __half* __restrict__ dst) {
    size_t i = (size_t)blockIdx.x * 256 + threadIdx.x;
    float4 v0 = src[2 * i];
    float4 v1 = src[2 * i + 1];
    half2 h[4];
    h[0] = __floats2half2_rn(v0.x, v0.y);
    h[1] = __floats2half2_rn(v0.z, v0.w);
    h[2] = __floats2half2_rn(v1.x, v1.y);
    h[3] = __floats2half2_rn(v1.z, v1.w);
    *reinterpret_cast<uint4*>(dst + 8 * i) = *reinterpret_cast<uint4*>(h);
}

// ============================================================================
// 1024x1024 fp32 -> fp16 transpose (z selects one of 3 weight matrices)
// ============================================================================
__global__ __launch_bounds__(256)
void transpose_f2h(const float* __restrict__ w0, const float* __restrict__ w1,
                   const float* __restrict__ w2) {
    __shared__ float t[32][33];
    int bz = blockIdx.z;
    const float* s = (bz == 0) ? w0 : (bz == 1 ? w1 : w2);
    __half* d = g_half + WQ + (size_t)bz * H1M;
    int x = blockIdx.x * 32 + threadIdx.x;
    int y0 = blockIdx.y * 32;
    for (int i = threadIdx.y; i < 32; i += 8)
        t[i][threadIdx.x] = s[(size_t)(y0 + i) * 1024 + x];
    __syncthreads();
    int ox = blockIdx.y * 32 + threadIdx.x;
    int oy0 = blockIdx.x * 32;
    for (int i = threadIdx.y; i < 32; i += 8)
        d[(size_t)(oy0 + i) * 1024 + ox] = __float2half_rn(t[threadIdx.x][i]);
}

// ============================================================================
// per-batch 1024x1024 fp16 transpose: VH [s][d] -> VTH [d][s]
// ============================================================================
__global__ __launch_bounds__(256)
void transpose_h2h() {
    __shared__ __half t[32][34];
    int bz = blockIdx.z;
    const __half* s = g_half + VH + (size_t)bz * H1M;
    __half* d = g_half + VTH + (size_t)bz * H1M;
    int x = blockIdx.x * 32 + threadIdx.x;
    int y0 = blockIdx.y * 32;
    for (int i = threadIdx.y; i < 32; i += 8)
        t[i][threadIdx.x] = s[(size_t)(y0 + i) * 1024 + x];
    __syncthreads();
    int ox = blockIdx.y * 32 + threadIdx.x;
    int oy0 = blockIdx.x * 32;
    for (int i = threadIdx.y; i < 32; i += 8)
        d[(size_t)(oy0 + i) * 1024 + ox] = t[threadIdx.x][i];
}

// ============================================================================
// Masked softmax over fp32 scores rows; writes fp16 probs.
// ============================================================================
__global__ __launch_bounds__(256)
void softmax_kernel(const float* __restrict__ mask) {
    __shared__ float red[8];
    int row = blockIdx.x;
    int b = row >> 10;
    int q = row & (SEQ - 1);
    const float* p = g_scores + (size_t)row * SEQ;
    __half* ph = g_half + PH + (size_t)row * SEQ;
    const float* mrow = mask + ((size_t)b * SEQ + q) * SEQ;

    int t = threadIdx.x;
    float4 s = ((const float4*)p)[t];
    float4 mm = ((const float4*)mrow)[t];
    s.x += (1.0f - mm.x) * -1e9f;
    s.y += (1.0f - mm.y) * -1e9f;
    s.z += (1.0f - mm.z) * -1e9f;
    s.w += (1.0f - mm.w) * -1e9f;

    float v = fmaxf(fmaxf(s.x, s.y), fmaxf(s.z, s.w));
#pragma unroll
    for (int o = 16; o; o >>= 1) v = fmaxf(v, __shfl_xor_sync(0xffffffffu, v, o));
    if ((t & 31) == 0) red[t >> 5] = v;
    __syncthreads();
    if (t < 32) {
        float x = (t < 8) ? red[t] : -3.4e38f;
#pragma unroll
        for (int o = 4; o; o >>= 1) x = fmaxf(x, __shfl_xor_sync(0xffffffffu, x, o));
        if (t == 0) red[0] = x;
    }
    __syncthreads();
    float rmax = red[0];

    float e0 = expf(s.x - rmax);
    float e1 = expf(s.y - rmax);
    float e2 = expf(s.z - rmax);
    float e3 = expf(s.w - rmax);

    __syncthreads();
    float sum = e0 + e1 + e2 + e3;
#pragma unroll
    for (int o = 16; o; o >>= 1) sum += __shfl_xor_sync(0xffffffffu, sum, o);
    if ((t & 31) == 0) red[t >> 5] = sum;
    __syncthreads();
    if (t < 32) {
        float x = (t < 8) ? red[t] : 0.0f;
#pragma unroll
        for (int o = 4; o; o >>= 1) x += __shfl_xor_sync(0xffffffffu, x, o);
        if (t == 0) red[0] = x;
    }
    __syncthreads();
    float inv = 1.0f / red[0];

    half2 h[2];
    h[0] = __floats2half2_rn(e0 * inv, e1 * inv);
    h[1] = __floats2half2_rn(e2 * inv, e3 * inv);
    *reinterpret_cast<uint2*>(ph + 4 * t) = *reinterpret_cast<uint2*>(h);
}

// ============================================================================
// Launch
// ============================================================================
extern "C" void kernel_launch(void* const* d_in, const int* in_sizes, int n_in,
                              void* d_out, int out_size) {
    const float* hidden = (const float*)d_in[0];
    const float* right  = (const float*)d_in[1];
    const float* mask   = (const float*)d_in[2];
    const float* Wq     = (const float*)d_in[3];
    const float* bq     = (const float*)d_in[4];
    const float* Wk     = (const float*)d_in[5];
    const float* bk     = (const float*)d_in[6];
    const float* Wv     = (const float*)d_in[7];
    const float* bv     = (const float*)d_in[8];
    float* out = (float*)d_out;

    __half* Hs = nullptr;
    cudaGetSymbolAddress((void**)&Hs, g_half);

    cudaFuncSetAttribute(hgemm<0>, cudaFuncAttributeMaxDynamicSharedMemorySize,
                         SMEM_BYTES);
    cudaFuncSetAttribute(hgemm<1>, cudaFuncAttributeMaxDynamicSharedMemorySize,
                         SMEM_BYTES);
    cudaFuncSetAttribute(hgemm<2>, cudaFuncAttributeMaxDynamicSharedMemorySize,
                         SMEM_BYTES);

    // 1) inputs -> fp16
    f2h<<<4096, 256>>>((const float4*)hidden, Hs + XH);
    f2h<<<4096, 256>>>((const float4*)right,  Hs + RH);

    // 2) weights -> fp16 K-major [n][k]
    transpose_f2h<<<dim3(32, 32, 3), dim3(32, 8)>>>(Wq, Wk, Wv);

    // 3) merged projections (z=0:Q scaled 0.125, 1:K, 2:V)
    hgemm<0><<<dim3(DIM / BN, (BATCH * SEQ) / BM, 3), 256, SMEM_BYTES>>>(
        bq, bk, bv, nullptr);

    // 4) V -> V^T per batch
    transpose_h2h<<<dim3(32, 32, BATCH), dim3(32, 8)>>>();

    // 5) scores: g_scores[b][i][j] = Q[b,i,:] . K[b,j,:]  (fp32)
    hgemm<1><<<dim3(SEQ / BN, SEQ / BM, BATCH), 256, SMEM_BYTES>>>(
        nullptr, nullptr, nullptr, nullptr);

    // 6) masked softmax -> fp16 probs
    softmax_kernel<<<BATCH * SEQ, 256>>>(mask);

    // 7) context: out[b][h][q][dh] = sum_j P[b][q][j] * VT[b][h*64+dh][j]
    hgemm<2><<<dim3(SEQ / BN, SEQ / BM, BATCH), 256, SMEM_BYTES>>>(
        nullptr, nullptr, nullptr, out);
}

// round 16
// speedup vs baseline: 6.8611x; 1.1852x over previous
#include <cuda_runtime.h>
#include <cuda_fp16.h>
#include <cstdint>

// ============================================================================
// Problem constants
// ============================================================================
#define BATCH 8
#define SEQ   1024
#define DIM   1024
#define HDIM  64

// ============================================================================
// Scratch (half + fp32 scores), element offsets
// ============================================================================
#define H1M (1u << 20)
#define XH  (0u  * H1M)   // hidden as fp16          (8M)
#define RH  (8u  * H1M)   // right as fp16           (8M)
#define QH  (16u * H1M)   // Q fp16 (scaled 0.125)   (8M)
#define KH  (24u * H1M)   // K fp16                  (8M)
#define VH  (32u * H1M)   // V fp16 [s][d]           (8M)
#define VTH (40u * H1M)   // V^T fp16 [d][s]         (8M)
#define PH  (48u * H1M)   // probs fp16              (8M)
#define WQ  (56u * H1M)   // Wq^T fp16 [n][k]; WK=+1M, WV=+2M

__device__ __align__(256) __half g_half[59u * H1M];
__device__ __align__(256) float  g_scores[8u * H1M];   // fp32 scores (32MB)

// ============================================================================
// GEMM tiling
// ============================================================================
#define BM     128
#define BN     128
#define BKH    64                 // halfs of K per stage (128 B/row)
#define SA     72                 // padded smem row stride (halfs, 144 B)
#define STAGES 3
#define NKI    (1024 / BKH)       // 16
#define SMEM_BYTES (STAGES * (BM + BN) * SA * 2)   // 110592 -> 2 CTAs/SM

// ============================================================================
// Device helpers
// ============================================================================
__device__ __forceinline__ uint32_t smem_u32(const void* p) {
    uint32_t a;
    asm("{ .reg .u64 t; cvta.to.shared.u64 t, %1; cvt.u32.u64 %0, t; }"
        : "=r"(a) : "l"(p));
    return a;
}

__device__ __forceinline__ void cp_async16(uint32_t saddr, const void* gaddr) {
    asm volatile("cp.async.cg.shared.global [%0], [%1], 16;"
                 :: "r"(saddr), "l"(gaddr) : "memory");
}

#define LDSM4(r0, r1, r2, r3, addr) \
    asm volatile("ldmatrix.sync.aligned.m8n8.x4.shared.b16 {%0,%1,%2,%3}, [%4];" \
                 : "=r"(r0), "=r"(r1), "=r"(r2), "=r"(r3) : "r"(addr))

__device__ __forceinline__ void mma16816(float* c, const uint32_t* a,
                                         const uint32_t* b) {
    asm volatile(
        "mma.sync.aligned.m16n8k16.row.col.f32.f16.f16.f32 "
        "{%0,%1,%2,%3}, {%4,%5,%6,%7}, {%8,%9}, {%0,%1,%2,%3};"
        : "+f"(c[0]), "+f"(c[1]), "+f"(c[2]), "+f"(c[3])
        : "r"(a[0]), "r"(a[1]), "r"(a[2]), "r"(a[3]), "r"(b[0]), "r"(b[1]));
}

// ============================================================================
// fp16 tensor-core GEMM:  D[BM x BN] = A[BM x 1024] . B[BN x 1024]^T
// (A row-major halfs, B K-major halfs; fp32 accumulate)
// MODE 0: merged projections (z: 0=Q,1=K,2=V), half output with bias+alpha
// MODE 1: scores -> g_scores fp32
// MODE 2: context -> permuted fp32 out
// ============================================================================
template <int MODE>
__global__ __launch_bounds__(256, 2)
void hgemm(const float* __restrict__ b0, const float* __restrict__ b1,
           const float* __restrict__ b2, float* __restrict__ outp) {
    extern __shared__ __half smh[];
    __half* As = smh;                            // [STAGES][BM][SA]
    __half* Bs = smh + STAGES * BM * SA;         // [STAGES][BN][SA]
    uint32_t sAb = smem_u32(As);
    uint32_t sBb = smem_u32(Bs);

    int tid = threadIdx.x;
    int wid = tid >> 5, lane = tid & 31;
    int wm = wid >> 2, wn = wid & 3;             // 2 x 4 warp grid
    int bx = blockIdx.x, by = blockIdx.y, bz = blockIdx.z;

    // ---- resolve operands from scratch ----
    const __half *Ag, *Bg;
    if (MODE == 0) {
        Ag = g_half + (bz == 0 ? XH : RH) + (size_t)by * BM * 1024;
        Bg = g_half + WQ + (size_t)bz * H1M + (size_t)bx * BN * 1024;
    } else if (MODE == 1) {
        Ag = g_half + QH + (size_t)bz * H1M + (size_t)by * BM * 1024;
        Bg = g_half + KH + (size_t)bz * H1M + (size_t)bx * BN * 1024;
    } else {
        Ag = g_half + PH + (size_t)bz * H1M + (size_t)by * BM * 1024;
        Bg = g_half + VTH + (size_t)bz * H1M + (size_t)bx * BN * 1024;
    }

    // ---- loader assignments: 1024 16B-chunks per matrix per stage ----
    int ldrow[4], ldc[4];
#pragma unroll
    for (int i = 0; i < 4; i++) {
        int idx = i * 256 + tid;
        ldrow[i] = idx >> 3;
        ldc[i] = idx & 7;
    }

    // ---- fragment smem byte offsets (within one stage) ----
    int r8 = lane & 7;
    int a_row = ((lane >> 3) & 1) * 8 + r8;
    int a_k   = (lane >> 4) * 8;
    uint32_t aoff[4];
#pragma unroll
    for (int mi = 0; mi < 4; mi++)
        aoff[mi] = ((wm * 64 + mi * 16 + a_row) * SA + a_k) * 2;
    int b_n = ((lane >> 4) & 1) * 8 + r8;
    int b_k = ((lane >> 3) & 1) * 8;
    uint32_t boff[2];
#pragma unroll
    for (int g = 0; g < 2; g++)
        boff[g] = ((wn * 32 + g * 16 + b_n) * SA + b_k) * 2;

    float acc[4][4][4];
#pragma unroll
    for (int mi = 0; mi < 4; mi++)
#pragma unroll
        for (int ni = 0; ni < 4; ni++)
#pragma unroll
            for (int c = 0; c < 4; c++) acc[mi][ni][c] = 0.0f;

    // ---- prologue: fill STAGES stages ----
#pragma unroll
    for (int s = 0; s < STAGES; s++) {
#pragma unroll
        for (int i = 0; i < 4; i++) {
            uint32_t so = (uint32_t)(ldrow[i] * SA + ldc[i] * 8) * 2;
            uint32_t sb = (uint32_t)(s * BM * SA * 2);
            cp_async16(sAb + sb + so, Ag + (size_t)ldrow[i] * 1024 + s * BKH + ldc[i] * 8);
            cp_async16(sBb + sb + so, Bg + (size_t)ldrow[i] * 1024 + s * BKH + ldc[i] * 8);
        }
        asm volatile("cp.async.commit_group;" ::: "memory");
    }

    // ---- main loop ----
    for (int ks = 0; ks < NKI; ks++) {
        int st = ks % STAGES;
        asm volatile("cp.async.wait_group %0;" :: "n"(STAGES - 1) : "memory");
        __syncthreads();

        uint32_t Ast = sAb + (uint32_t)(st * BM * SA * 2);
        uint32_t Bst = sBb + (uint32_t)(st * BN * SA * 2);

#pragma unroll
        for (int k16 = 0; k16 < BKH / 16; k16++) {
            uint32_t kk = k16 * 32;   // 16 halfs = 32 bytes
            uint32_t afr[4][4];
#pragma unroll
            for (int mi = 0; mi < 4; mi++)
                LDSM4(afr[mi][0], afr[mi][1], afr[mi][2], afr[mi][3],
                      Ast + aoff[mi] + kk);
            uint32_t bfr[4][2];
            LDSM4(bfr[0][0], bfr[0][1], bfr[1][0], bfr[1][1], Bst + boff[0] + kk);
            LDSM4(bfr[2][0], bfr[2][1], bfr[3][0], bfr[3][1], Bst + boff[1] + kk);
#pragma unroll
            for (int mi = 0; mi < 4; mi++)
#pragma unroll
                for (int ni = 0; ni < 4; ni++)
                    mma16816(acc[mi][ni], afr[mi], bfr[ni]);
        }
        __syncthreads();

        int kn = ks + STAGES;
        if (kn < NKI) {
#pragma unroll
            for (int i = 0; i < 4; i++) {
                uint32_t so = (uint32_t)(ldrow[i] * SA + ldc[i] * 8) * 2;
                uint32_t sb = (uint32_t)(st * BM * SA * 2);
                cp_async16(sAb + sb + so,
                           Ag + (size_t)ldrow[i] * 1024 + kn * BKH + ldc[i] * 8);
                cp_async16(sBb + sb + so,
                           Bg + (size_t)ldrow[i] * 1024 + kn * BKH + ldc[i] * 8);
            }
        }
        asm volatile("cp.async.commit_group;" ::: "memory");
    }

    // ---- epilogue ----
    int crow = lane >> 2;
    int ccol = (lane & 3) * 2;

    if (MODE == 0) {
        const float* bias = (bz == 0) ? b0 : (bz == 1 ? b1 : b2);
        float alpha = (bz == 0) ? 0.125f : 1.0f;
        __half* Ch = g_half + QH + (size_t)bz * 8 * H1M;
#pragma unroll
        for (int mi = 0; mi < 4; mi++) {
            int gm = by * BM + wm * 64 + mi * 16 + crow;
            __half* r0 = Ch + (size_t)gm * 1024;
            __half* r1 = r0 + (size_t)8 * 1024;
#pragma unroll
            for (int ni = 0; ni < 4; ni++) {
                int gn = bx * BN + wn * 32 + ni * 8 + ccol;
                const float* a4 = acc[mi][ni];
                float bb0 = bias[gn], bb1 = bias[gn + 1];
                *(half2*)(r0 + gn) =
                    __floats2half2_rn(alpha * (a4[0] + bb0), alpha * (a4[1] + bb1));
                *(half2*)(r1 + gn) =
                    __floats2half2_rn(alpha * (a4[2] + bb0), alpha * (a4[3] + bb1));
            }
        }
    } else if (MODE == 1) {
        float* Cf = g_scores + (size_t)bz * H1M;
#pragma unroll
        for (int mi = 0; mi < 4; mi++) {
            int gm = by * BM + wm * 64 + mi * 16 + crow;
            float* r0 = Cf + (size_t)gm * 1024;
            float* r1 = r0 + (size_t)8 * 1024;
#pragma unroll
            for (int ni = 0; ni < 4; ni++) {
                int gn = bx * BN + wn * 32 + ni * 8 + ccol;
                const float* a4 = acc[mi][ni];
                *(float2*)(r0 + gn) = make_float2(a4[0], a4[1]);
                *(float2*)(r1 + gn) = make_float2(a4[2], a4[3]);
            }
        }
    } else {
        float* obase = outp + (size_t)bz * SEQ * DIM;
#pragma unroll
        for (int mi = 0; mi < 4; mi++) {
            int q = by * BM + wm * 64 + mi * 16 + crow;
#pragma unroll
            for (int ni = 0; ni < 4; ni++) {
                int gn = bx * BN + wn * 32 + ni * 8 + ccol;
                int h = gn >> 6, dh = gn & 63;
                float* dst = obase + ((size_t)h * SEQ + q) * HDIM + dh;
                const float* a4 = acc[mi][ni];
                *(float2*)dst = make_float2(a4[0], a4[1]);
                *(float2*)(dst + (size_t)8 * HDIM) = make_float2(a4[2], a4[3]);
            }
        }
    }
}

// ============================================================================
// fp32 -> fp16 copy (8 elems / thread)
// ============================================================================
__global__ __launch_bounds__(256)
void f2h(const float4* __restrict__ src, __half* __restrict__ dst) {
    size_t i = (size_t)blockIdx.x * 256 + threadIdx.x;
    float4 v0 = src[2 * i];
    float4 v1 = src[2 * i + 1];
    half2 h[4];
    h[0] = __floats2half2_rn(v0.x, v0.y);
    h[1] = __floats2half2_rn(v0.z, v0.w);
    h[2] = __floats2half2_rn(v1.x, v1.y);
    h[3] = __floats2half2_rn(v1.z, v1.w);
    *reinterpret_cast<uint4*>(dst + 8 * i) = *reinterpret_cast<uint4*>(h);
}

// ============================================================================
// 1024x1024 fp32 -> fp16 transpose (z selects one of 3 weight matrices)
// ============================================================================
__global__ __launch_bounds__(256)
void transpose_f2h(const float* __restrict__ w0, const float* __restrict__ w1,
                   const float* __restrict__ w2) {
    __shared__ float t[32][33];
    int bz = blockIdx.z;
    const float* s = (bz == 0) ? w0 : (bz == 1 ? w1 : w2);
    __half* d = g_half + WQ + (size_t)bz * H1M;
    int x = blockIdx.x * 32 + threadIdx.x;
    int y0 = blockIdx.y * 32;
    for (int i = threadIdx.y; i < 32; i += 8)
        t[i][threadIdx.x] = s[(size_t)(y0 + i) * 1024 + x];
    __syncthreads();
    int ox = blockIdx.y * 32 + threadIdx.x;
    int oy0 = blockIdx.x * 32;
    for (int i = threadIdx.y; i < 32; i += 8)
        d[(size_t)(oy0 + i) * 1024 + ox] = __float2half_rn(t[threadIdx.x][i]);
}

// ============================================================================
// per-batch 1024x1024 fp16 transpose: VH [s][d] -> VTH [d][s]
// ============================================================================
__global__ __launch_bounds__(256)
void transpose_h2h() {
    __shared__ __half t[32][34];
    int bz = blockIdx.z;
    const __half* s = g_half + VH + (size_t)bz * H1M;
    __half* d = g_half + VTH + (size_t)bz * H1M;
    int x = blockIdx.x * 32 + threadIdx.x;
    int y0 = blockIdx.y * 32;
    for (int i = threadIdx.y; i < 32; i += 8)
        t[i][threadIdx.x] = s[(size_t)(y0 + i) * 1024 + x];
    __syncthreads();
    int ox = blockIdx.y * 32 + threadIdx.x;
    int oy0 = blockIdx.x * 32;
    for (int i = threadIdx.y; i < 32; i += 8)
        d[(size_t)(oy0 + i) * 1024 + ox] = t[threadIdx.x][i];
}

// ============================================================================
// Masked softmax over fp32 scores rows; writes fp16 probs.
// ============================================================================
__global__ __launch_bounds__(256)
void softmax_kernel(const float* __restrict__ mask) {
    __shared__ float red[8];
    int row = blockIdx.x;
    int b = row >> 10;
    int q = row & (SEQ - 1);
    const float* p = g_scores + (size_t)row * SEQ;
    __half* ph = g_half + PH + (size_t)row * SEQ;
    const float* mrow = mask + ((size_t)b * SEQ + q) * SEQ;

    int t = threadIdx.x;
    float4 s = ((const float4*)p)[t];
    float4 mm = ((const float4*)mrow)[t];
    s.x += (1.0f - mm.x) * -1e9f;
    s.y += (1.0f - mm.y) * -1e9f;
    s.z += (1.0f - mm.z) * -1e9f;
    s.w += (1.0f - mm.w) * -1e9f;

    float v = fmaxf(fmaxf(s.x, s.y), fmaxf(s.z, s.w));
#pragma unroll
    for (int o = 16; o; o >>= 1) v = fmaxf(v, __shfl_xor_sync(0xffffffffu, v, o));
    if ((t & 31) == 0) red[t >> 5] = v;
    __syncthreads();
    if (t < 32) {
        float x = (t < 8) ? red[t] : -3.4e38f;
#pragma unroll
        for (int o = 4; o; o >>= 1) x = fmaxf(x, __shfl_xor_sync(0xffffffffu, x, o));
        if (t == 0) red[0] = x;
    }
    __syncthreads();
    float rmax = red[0];

    float e0 = expf(s.x - rmax);
    float e1 = expf(s.y - rmax);
    float e2 = expf(s.z - rmax);
    float e3 = expf(s.w - rmax);

    __syncthreads();
    float sum = e0 + e1 + e2 + e3;
#pragma unroll
    for (int o = 16; o; o >>= 1) sum += __shfl_xor_sync(0xffffffffu, sum, o);
    if ((t & 31) == 0) red[t >> 5] = sum;
    __syncthreads();
    if (t < 32) {
        float x = (t < 8) ? red[t] : 0.0f;
#pragma unroll
        for (int o = 4; o; o >>= 1) x += __shfl_xor_sync(0xffffffffu, x, o);
        if (t == 0) red[0] = x;
    }
    __syncthreads();
    float inv = 1.0f / red[0];

    half2 h[2];
    h[0] = __floats2half2_rn(e0 * inv, e1 * inv);
    h[1] = __floats2half2_rn(e2 * inv, e3 * inv);
    *reinterpret_cast<uint2*>(ph + 4 * t) = *reinterpret_cast<uint2*>(h);
}

// ============================================================================
// Launch
// ============================================================================
extern "C" void kernel_launch(void* const* d_in, const int* in_sizes, int n_in,
                              void* d_out, int out_size) {
    const float* hidden = (const float*)d_in[0];
    const float* right  = (const float*)d_in[1];
    const float* mask   = (const float*)d_in[2];
    const float* Wq     = (const float*)d_in[3];
    const float* bq     = (const float*)d_in[4];
    const float* Wk     = (const float*)d_in[5];
    const float* bk     = (const float*)d_in[6];
    const float* Wv     = (const float*)d_in[7];
    const float* bv     = (const float*)d_in[8];
    float* out = (float*)d_out;

    __half* Hs = nullptr;
    cudaGetSymbolAddress((void**)&Hs, g_half);

    cudaFuncSetAttribute(hgemm<0>, cudaFuncAttributeMaxDynamicSharedMemorySize,
                         SMEM_BYTES);
    cudaFuncSetAttribute(hgemm<1>, cudaFuncAttributeMaxDynamicSharedMemorySize,
                         SMEM_BYTES);
    cudaFuncSetAttribute(hgemm<2>, cudaFuncAttributeMaxDynamicSharedMemorySize,
                         SMEM_BYTES);

    // 1) inputs -> fp16
    f2h<<<4096, 256>>>((const float4*)hidden, Hs + XH);
    f2h<<<4096, 256>>>((const float4*)right,  Hs + RH);

    // 2) weights -> fp16 K-major [n][k]
    transpose_f2h<<<dim3(32, 32, 3), dim3(32, 8)>>>(Wq, Wk, Wv);

    // 3) merged projections (z=0:Q scaled 0.125, 1:K, 2:V)
    hgemm<0><<<dim3(DIM / BN, (BATCH * SEQ) / BM, 3), 256, SMEM_BYTES>>>(
        bq, bk, bv, nullptr);

    // 4) V -> V^T per batch
    transpose_h2h<<<dim3(32, 32, BATCH), dim3(32, 8)>>>();

    // 5) scores: g_scores[b][i][j] = Q[b,i,:] . K[b,j,:]  (fp32)
    hgemm<1><<<dim3(SEQ / BN, SEQ / BM, BATCH), 256, SMEM_BYTES>>>(
        nullptr, nullptr, nullptr, nullptr);

    // 6) masked softmax -> fp16 probs
    softmax_kernel<<<BATCH * SEQ, 256>>>(mask);

    // 7) context: out[b][h][q][dh] = sum_j P[b][q][j] * VT[b][h*64+dh][j]
    hgemm<2><<<dim3(SEQ / BN, SEQ / BM, BATCH), 256, SMEM_BYTES>>>(
        nullptr, nullptr, nullptr, out);
}